// round 9
// baseline (speedup 1.0000x reference)
#include <cuda_runtime.h>
#include <math.h>

#define BATCH 64
#define NPART 512
#define SPLIT 2
#define BLK   512
#define NW    (BLK / 32)         // 16 warps; each warp is one binning group
#define NGRP  NW
#define GRID  (BATCH * SPLIT)    // 128 CTAs = 64 clusters of 2

// Scratch (no allocation allowed).
__device__ float2 g_batch[BATCH];     // per-batch (nz, zz)
__device__ int    g_ticket;           // global arrival counter (reset in-kernel)

__device__ __forceinline__ unsigned smem_u32(const void* p) {
    unsigned a;
    asm("{ .reg .u64 t; cvta.to.shared.u64 t, %1; cvt.u32.u64 %0, t; }"
        : "=r"(a) : "l"(p));
    return a;
}
__device__ __forceinline__ unsigned mapa_rank(unsigned addr, unsigned rank) {
    unsigned r;
    asm("mapa.shared::cluster.u32 %0, %1, %2;" : "=r"(r) : "r"(addr), "r"(rank));
    return r;
}

__global__ __launch_bounds__(BLK) __cluster_dims__(2, 1, 1)
void chamfer_fused(const float4* __restrict__ target,
                   const float4* __restrict__ reco,
                   const int*    __restrict__ in_pid,
                   const int*    __restrict__ out_pid,
                   float* __restrict__ out, int out_size)
{
    __shared__ float4 sT[NPART], sR[NPART];      // class-compacted particles
    __shared__ float  sQT[NPART], sQR[NPART];    // 0.5*|p|^2 (compacted)
    __shared__ int    bX[NGRP][5], bY[NGRP][5];  // group counts -> group prefixes
    __shared__ int    offX[6], offY[6];
    __shared__ float  xacc[10];                  // [0..4]=accA, [5..9]=accB
    __shared__ float  pbuf[10];                  // partner partials (st.async dest)
    __shared__ alignas(8) unsigned long long mbar;  // rank0's arrival barrier
    __shared__ float  mNT[5], mNR[5];            // per-class norm sums (rank0 only)
    __shared__ float  snz[BATCH], szz[BATCH];    // final gather (last CTA)
    __shared__ int    fl;

    const int b    = blockIdx.x >> 1;
    const int s    = blockIdx.x & 1;             // cluster rank
    const int tid  = threadIdx.x;
    const int w    = tid >> 5;
    const int lane = tid & 31;
    const unsigned lt = (1u << lane) - 1u;

    // rank0: init export barrier FIRST (remote st.asyncs arrive >~4000cyc later)
    if (s == 0 && tid == 0) {
        const unsigned mb = smem_u32(&mbar);
        asm volatile("mbarrier.init.shared.b64 [%0], 1;" :: "r"(mb) : "memory");
        asm volatile("fence.mbarrier_init.release.cluster;" ::: "memory");
    }
    if (tid < 10) xacc[tid] = 0.f;
    // per-warp bin zeroing (each warp owns its own bin rows)
    if (lane < 5) { bX[w][lane] = 0; bY[w][lane] = 0; }
    __syncwarp();

    const float4* Tb  = target  + b * NPART;
    const float4* Rb  = reco    + b * NPART;
    const int*    IPb = in_pid  + b * NPART;
    const int*    OPb = out_pid + b * NPART;

    // ---- Load (1 target + 1 reco per thread) + atomic-free binning ----
    const float4 tv = Tb[tid];
    const float4 rv = Rb[tid];
    const int    tp = IPb[tid];
    const int    rp = OPb[tid];
    const unsigned mX = __match_any_sync(0xffffffffu, tp);
    const unsigned mY = __match_any_sync(0xffffffffu, rp);
    const int rkX = __popc(mX & lt);
    const int rkY = __popc(mY & lt);
    if (rkX == 0) bX[w][tp] = __popc(mX);
    if (rkY == 0) bY[w][rp] = __popc(mY);
    __syncthreads();                             // #1: all bins visible

    // ---- Scan (all inside warp 0: syncwarp instead of block barriers) ----
    if (w == 0) {
        int run = 0;
        if (tid < 10) {
            const int side = tid / 5, q = tid % 5;
            int (*bb)[5] = side ? bY : bX;
            int v[NGRP];
#pragma unroll
            for (int g = 0; g < NGRP; g++) v[g] = bb[g][q];
#pragma unroll
            for (int g = 0; g < NGRP; g++) { const int c = v[g]; bb[g][q] = run; run += c; }
        }
        // class totals live in lanes 0..9; warp-scan them into offsets
        __syncwarp();
        if (tid == 0) {
            // totals via direct recompute from lane regs is cross-lane; simplest:
        }
        // gather totals via shuffle: lane q holds tot for (side=0,q), lane 5+q for side 1
        {
            int a0 = 0, a1 = 0;
            if (tid == 0) {
                // nothing; handled below by lanes 0 and 1 using shuffles
            }
            // broadcast each lane's run to lane 0/1 and accumulate serially (10 shfl)
            int myrun = (tid < 10) ? run : 0;
#pragma unroll
            for (int q = 0; q < 5; q++) {
                const int tX = __shfl_sync(0xffffffffu, myrun, q);
                const int tY = __shfl_sync(0xffffffffu, myrun, 5 + q);
                if (tid == 0) { offX[q] = a0; a0 += tX; }
                if (tid == 1) { offY[q] = a1; a1 += tY; }
            }
            if (tid == 0) offX[5] = a0;
            if (tid == 1) offY[5] = a1;
        }
    }
    __syncthreads();                             // #2: bins(prefixed)+offsets visible

    // ---- Deterministic scatter (no atomics): particle + half-sq-norm ----
    {
        const int ix = offX[tp] + bX[w][tp] + rkX;
        const int iy = offY[rp] + bY[w][rp] + rkY;
        sT[ix] = tv;  sQT[ix] = 0.5f * (tv.x*tv.x + tv.y*tv.y + tv.z*tv.z + tv.w*tv.w);
        sR[iy] = rv;  sQR[iy] = 0.5f * (rv.x*rv.x + rv.y*rv.y + rv.z*rv.z + rv.w*rv.w);
    }
    __syncthreads();                             // #3: compacted arrays visible

    // ---- Per-class norm sums (rank 0 only; before min-loop, off the tail) ----
    if (s == 0) {
        for (int seg = w; seg < 9; seg += NW) {
            int lo, hi; const float* qq;
            if (seg < 4) { qq = sQT; lo = offX[seg + 1]; hi = offX[seg + 2]; }
            else         { qq = sQR; lo = offY[seg - 4]; hi = offY[seg - 3]; }
            float sum = 0.f;
            for (int j = lo + lane; j < hi; j += 32) sum += sqrtf(2.f * qq[j]);
#pragma unroll
            for (int o = 16; o; o >>= 1) sum += __shfl_down_sync(0xffffffffu, sum, o);
            if (lane == 0) {
                if (seg < 4)       mNT[seg + 1] = sum;
                else if (seg == 4) mNR[0]       = sum;
                else               mNR[seg - 4] = sum;
            }
        }
    }

    // ---- Main work: one item per thread (classes 1..4 only) ----
    // min_j |x-y_j|^2 = |x|^2 + 2*min_j(h_j - x.y_j),  h_j = 0.5|y_j|^2
    const int nA = NPART - offX[1];
    const int nB = NPART - offY[1];
    const int m  = s * BLK + tid;

    if (m < nA + nB) {
        const bool passA = (m < nA);
        int k = passA ? (offX[1] + m) : (offY[1] + (m - nA));
        const int* off_self  = passA ? offX : offY;
        const int* off_other = passA ? offY : offX;

        int q = 1;
        while (k >= off_self[q + 1]) q++;

        const int jb = off_other[q], je = off_other[q + 1];
        if (jb != je) {
            const float4  x     = passA ? sT[k]  : sR[k];
            const float   xsq   = 2.f * (passA ? sQT[k] : sQR[k]);
            const float4* other = passA ? sR  : sT;
            const float*  hoth  = passA ? sQR : sQT;
            const float nx = -x.x, ny = -x.y, nz = -x.z, nw = -x.w;

            float ms0 = INFINITY, ms1 = INFINITY;
            int j = jb;
            if ((je - jb) & 1) {
                const float4 y = other[j];
                ms0 = fmaf(nx, y.x, fmaf(ny, y.y, fmaf(nz, y.z, fmaf(nw, y.w, hoth[j]))));
                j++;
            }
#pragma unroll 4
            for (; j < je; j += 2) {
                const float4 y0 = other[j];
                const float4 y1 = other[j + 1];
                const float s0 = fmaf(nx, y0.x, fmaf(ny, y0.y, fmaf(nz, y0.z, fmaf(nw, y0.w, hoth[j]))));
                const float s1 = fmaf(nx, y1.x, fmaf(ny, y1.y, fmaf(nz, y1.z, fmaf(nw, y1.w, hoth[j + 1]))));
                ms0 = fminf(ms0, s0);
                ms1 = fminf(ms1, s1);
            }
            const float ms = fminf(ms0, ms1);
            const float d2 = fmaxf(fmaf(2.f, ms, xsq), 0.f);
            atomicAdd(&xacc[(passA ? 0 : 5) + q], sqrtf(d2));
        }
    }
    __syncthreads();                             // #4: xacc final in both CTAs

    // ---- rank1: push partials into rank0's pbuf via st.async, then exit ----
    if (s == 1) {
        if (tid < 10) {
            const unsigned raddr = mapa_rank(smem_u32(&pbuf[tid]), 0);
            const unsigned rmbar = mapa_rank(smem_u32(&mbar), 0);
            const float v = xacc[tid];
            asm volatile(
                "st.async.shared::cluster.mbarrier::complete_tx::bytes.b32 [%0], %1, [%2];"
                :: "r"(raddr), "r"(__float_as_uint(v)), "r"(rmbar) : "memory");
        }
        return;
    }

    // ---- rank0: wait for partner's 40 bytes, combine, ticket ----
    if (tid == 0) {
        const unsigned mb = smem_u32(&mbar);
        asm volatile("mbarrier.arrive.expect_tx.shared.b64 _, [%0], 40;" :: "r"(mb) : "memory");
        unsigned done;
        asm volatile(
            "{\n\t.reg .pred p;\n\t"
            "WAITLP:\n\t"
            "mbarrier.try_wait.parity.acquire.cta.shared::cta.b64 p, [%1], 0, 0x989680;\n\t"
            "selp.b32 %0, 1, 0, p;\n\t"
            "@!p bra WAITLP;\n\t}"
            : "=r"(done) : "r"(mb) : "memory");

        float nzsum = 0.f;
#pragma unroll
        for (int q = 1; q < 5; q++) {
            const float cx = (float)(offX[q + 1] - offX[q]);
            const float cy = (float)(offY[q + 1] - offY[q]);
            float per;
            if (cy == 0.f)      per = mNT[q] / fmaxf(1.f, cx);
            else if (cx == 0.f) per = mNR[q] / fmaxf(1.f, cy);
            else                per = 0.5f * ((xacc[q] + pbuf[q]) / fmaxf(1.f, cy)
                                            + (xacc[5 + q] + pbuf[5 + q]) / fmaxf(1.f, cx));
            nzsum += per;
        }
        float2 res;
        res.x = nzsum;
        res.y = mNR[0] / fmaxf(1.f, (float)(offY[1] - offY[0]));
        g_batch[b] = res;
        __threadfence();                         // order STG before ticket
        fl = (atomicAdd(&g_ticket, 1) == BATCH - 1);
    }
    __syncthreads();                             // #5: broadcast fl
    if (!fl) return;

    // ---- Last CTA: final combine over 64 batches ----
    __threadfence();                             // acquire all g_batch
    if (tid < BATCH) {
        const float2 vv = __ldcg(&g_batch[tid]);
        snz[tid] = vv.x;
        szz[tid] = vv.y;
    }
    __syncthreads();
    if (tid < 32) {
        float a = snz[tid] + snz[tid + 32];
        float c = szz[tid] + szz[tid + 32];
#pragma unroll
        for (int o = 16; o; o >>= 1) {
            a += __shfl_down_sync(0xffffffffu, a, o);
            c += __shfl_down_sync(0xffffffffu, c, o);
        }
        if (tid == 0) {
            out[0] = a / (float)BATCH;
            if (out_size > 1) out[1] = c / (float)BATCH;
            g_ticket = 0;                        // reset for next graph replay
        }
    }
}

extern "C" void kernel_launch(void* const* d_in, const int* in_sizes, int n_in,
                              void* d_out, int out_size)
{
    const float4* target = (const float4*)d_in[0];
    const float4* reco   = (const float4*)d_in[1];
    const int*    ipid   = (const int*)d_in[2];
    const int*    opid   = (const int*)d_in[3];
    float*        out    = (float*)d_out;
    (void)in_sizes; (void)n_in;

    chamfer_fused<<<GRID, BLK>>>(target, reco, ipid, opid, out, out_size);
}

// round 10
// speedup vs baseline: 1.0626x; 1.0626x over previous
#include <cuda_runtime.h>
#include <math.h>

#define BATCH 64
#define NPART 512
#define BLK   1024               // 32 warps: 16 target-side, 16 reco-side
#define GRID  (BATCH * 2)       // 128 CTAs = 64 clusters of 2
#define NW    (BLK / 32)
#define NGRP  16                 // binning groups per side

// Scratch (no allocation allowed).
__device__ float2 g_batch[BATCH];     // per-batch (nz, zz)
__device__ int    g_ticket;           // global arrival counter (reset in-kernel)

__device__ __forceinline__ unsigned smem_u32(const void* p) {
    unsigned a;
    asm("{ .reg .u64 t; cvta.to.shared.u64 t, %1; cvt.u32.u64 %0, t; }"
        : "=r"(a) : "l"(p));
    return a;
}
__device__ __forceinline__ unsigned mapa_rank(unsigned addr, unsigned rank) {
    unsigned r;
    asm("mapa.shared::cluster.u32 %0, %1, %2;" : "=r"(r) : "r"(addr), "r"(rank));
    return r;
}

__global__ __launch_bounds__(BLK) __cluster_dims__(2, 1, 1)
void chamfer_fused(const float4* __restrict__ target,
                   const float4* __restrict__ reco,
                   const int*    __restrict__ in_pid,
                   const int*    __restrict__ out_pid,
                   float* __restrict__ out, int out_size)
{
    __shared__ float4 sT[NPART], sR[NPART];      // class-compacted particles
    __shared__ float  sQT[NPART], sQR[NPART];    // 0.5*|p|^2 (compacted)
    __shared__ int    bX[NGRP][5], bY[NGRP][5];  // group counts -> group prefixes
    __shared__ int    offX[6], offY[6];
    __shared__ float  xacc[10];                  // [0..4]=accA, [5..9]=accB
    __shared__ float  pbuf[10];                  // partner partials (st.async dest)
    __shared__ alignas(8) unsigned long long mbar;  // rank0's arrival barrier
    __shared__ float  mNT[5], mNR[5];            // per-class norm sums (rank0 only)
    __shared__ float  snz[BATCH], szz[BATCH];    // final gather (last CTA)
    __shared__ int    fl;

    const int b    = blockIdx.x >> 1;
    const int s    = blockIdx.x & 1;             // cluster rank
    const int tid  = threadIdx.x;
    const int w    = tid >> 5;
    const int lane = tid & 31;
    const int side = tid >> 9;                   // 0 = target, 1 = reco
    const int i    = tid & (NPART - 1);          // particle index within side
    const int g    = w & (NGRP - 1);             // binning group within side
    const unsigned lt = (1u << lane) - 1u;

    // rank0: init export barrier FIRST (remote st.asyncs arrive much later)
    if (s == 0 && tid == 0) {
        const unsigned mb = smem_u32(&mbar);
        asm volatile("mbarrier.init.shared.b64 [%0], 1;" :: "r"(mb) : "memory");
        asm volatile("fence.mbarrier_init.release.cluster;" ::: "memory");
    }
    if (tid < 10) xacc[tid] = 0.f;
    // per-warp bin zeroing (each warp owns its own bin row)
    if (lane < 5) { if (side) bY[g][lane] = 0; else bX[g][lane] = 0; }
    __syncwarp();

    // ---- Load (1 particle per thread) + atomic-free binning ----
    const float4 v = side ? reco[b * NPART + i]    : target[b * NPART + i];
    const int    p = side ? out_pid[b * NPART + i] : in_pid[b * NPART + i];

    const unsigned mm = __match_any_sync(0xffffffffu, p);  // warp is side-uniform
    const int rk = __popc(mm & lt);
    if (rk == 0) { if (side) bY[g][p] = __popc(mm); else bX[g][p] = __popc(mm); }
    __syncthreads();                             // #1: all bins visible

    // ---- Scan (inside warp 0: syncwarp instead of block barriers) ----
    if (w == 0) {
        int run = 0;
        if (tid < 10) {
            const int sd = tid / 5, q = tid % 5;
            int (*bb)[5] = sd ? bY : bX;
            int vv[NGRP];
#pragma unroll
            for (int gg = 0; gg < NGRP; gg++) vv[gg] = bb[gg][q];
#pragma unroll
            for (int gg = 0; gg < NGRP; gg++) { const int c = vv[gg]; bb[gg][q] = run; run += c; }
        }
        __syncwarp();
        {
            int a0 = 0, a1 = 0;
            const int myrun = (tid < 10) ? run : 0;
#pragma unroll
            for (int q = 0; q < 5; q++) {
                const int tX = __shfl_sync(0xffffffffu, myrun, q);
                const int tY = __shfl_sync(0xffffffffu, myrun, 5 + q);
                if (tid == 0) { offX[q] = a0; a0 += tX; }
                if (tid == 1) { offY[q] = a1; a1 += tY; }
            }
            if (tid == 0) offX[5] = a0;
            if (tid == 1) offY[5] = a1;
        }
    }
    __syncthreads();                             // #2: prefixed bins + offsets

    // ---- Deterministic scatter (no atomics): particle + half-sq-norm ----
    {
        const float q2 = v.x*v.x + v.y*v.y + v.z*v.z + v.w*v.w;
        if (side) {
            const int iy = offY[p] + bY[g][p] + rk;
            sR[iy] = v;  sQR[iy] = 0.5f * q2;
        } else {
            const int ix = offX[p] + bX[g][p] + rk;
            sT[ix] = v;  sQT[ix] = 0.5f * q2;
        }
    }
    __syncthreads();                             // #3: compacted arrays visible

    // ---- Per-class norm sums (rank 0 only; off the tail) ----
    if (s == 0 && w < 9) {
        const int seg = w;
        int lo, hi; const float* qq;
        if (seg < 4) { qq = sQT; lo = offX[seg + 1]; hi = offX[seg + 2]; }
        else         { qq = sQR; lo = offY[seg - 4]; hi = offY[seg - 3]; }
        float sum = 0.f;
        for (int j = lo + lane; j < hi; j += 32) sum += sqrtf(2.f * qq[j]);
#pragma unroll
        for (int o = 16; o; o >>= 1) sum += __shfl_down_sync(0xffffffffu, sum, o);
        if (lane == 0) {
            if (seg < 4)       mNT[seg + 1] = sum;
            else if (seg == 4) mNR[0]       = sum;
            else               mNR[seg - 4] = sum;
        }
    }

    // ---- Main work: one item per THREAD PAIR (even/odd j-parity) ----
    // min_j |x-y_j|^2 = |x|^2 + 2*min_j(h_j - x.y_j),  h_j = 0.5|y_j|^2
    const int nA = NPART - offX[1];
    const int nB = NPART - offY[1];
    const int m    = s * (BLK / 2) + (tid >> 1); // item index; 1024 items/batch
    const int half = tid & 1;

    float ms = INFINITY;
    bool  doit = false, passA = false;
    int   q = 1;
    float xsq = 0.f;

    if (m < nA + nB) {
        passA = (m < nA);
        int k = passA ? (offX[1] + m) : (offY[1] + (m - nA));
        const int* off_self  = passA ? offX : offY;
        const int* off_other = passA ? offY : offX;

        while (k >= off_self[q + 1]) q++;

        const int jb = off_other[q], je = off_other[q + 1];
        if (jb != je) {
            doit = true;
            const float4  x     = passA ? sT[k]  : sR[k];
            xsq                 = 2.f * (passA ? sQT[k] : sQR[k]);
            const float4* other = passA ? sR  : sT;
            const float*  hoth  = passA ? sQR : sQT;
            const float nx = -x.x, ny = -x.y, nz = -x.z, nw = -x.w;

            float ms0 = INFINITY, ms1 = INFINITY;
            int j = jb + half;
            // 2-stride scan with 2 accumulators for ILP (4 j's in flight/pair)
            for (; j + 2 < je; j += 4) {
                const float4 y0 = other[j];
                const float4 y1 = other[j + 2];
                const float s0 = fmaf(nx, y0.x, fmaf(ny, y0.y, fmaf(nz, y0.z, fmaf(nw, y0.w, hoth[j]))));
                const float s1 = fmaf(nx, y1.x, fmaf(ny, y1.y, fmaf(nz, y1.z, fmaf(nw, y1.w, hoth[j + 2]))));
                ms0 = fminf(ms0, s0);
                ms1 = fminf(ms1, s1);
            }
            if (j < je) {
                const float4 y = other[j];
                ms0 = fminf(ms0, fmaf(nx, y.x, fmaf(ny, y.y, fmaf(nz, y.z, fmaf(nw, y.w, hoth[j])))));
            }
            ms = fminf(ms0, ms1);
        }
    }
    // combine pair halves (partner = lane^1, same warp)
    ms = fminf(ms, __shfl_xor_sync(0xffffffffu, ms, 1));
    if (doit && half == 0) {
        const float d2 = fmaxf(fmaf(2.f, ms, xsq), 0.f);
        atomicAdd(&xacc[(passA ? 0 : 5) + q], sqrtf(d2));
    }
    __syncthreads();                             // #4: xacc final in both CTAs

    // ---- rank1: push partials into rank0's pbuf via st.async, then exit ----
    if (s == 1) {
        if (tid < 10) {
            const unsigned raddr = mapa_rank(smem_u32(&pbuf[tid]), 0);
            const unsigned rmbar = mapa_rank(smem_u32(&mbar), 0);
            const float vv = xacc[tid];
            asm volatile(
                "st.async.shared::cluster.mbarrier::complete_tx::bytes.b32 [%0], %1, [%2];"
                :: "r"(raddr), "r"(__float_as_uint(vv)), "r"(rmbar) : "memory");
        }
        return;
    }

    // ---- rank0: wait for partner's 40 bytes, combine, ticket ----
    if (tid == 0) {
        const unsigned mb = smem_u32(&mbar);
        asm volatile("mbarrier.arrive.expect_tx.shared.b64 _, [%0], 40;" :: "r"(mb) : "memory");
        unsigned done;
        asm volatile(
            "{\n\t.reg .pred p;\n\t"
            "WAITLP:\n\t"
            "mbarrier.try_wait.parity.acquire.cta.shared::cta.b64 p, [%1], 0, 0x989680;\n\t"
            "selp.b32 %0, 1, 0, p;\n\t"
            "@!p bra WAITLP;\n\t}"
            : "=r"(done) : "r"(mb) : "memory");

        float nzsum = 0.f;
#pragma unroll
        for (int qq = 1; qq < 5; qq++) {
            const float cx = (float)(offX[qq + 1] - offX[qq]);
            const float cy = (float)(offY[qq + 1] - offY[qq]);
            float per;
            if (cy == 0.f)      per = mNT[qq] / fmaxf(1.f, cx);
            else if (cx == 0.f) per = mNR[qq] / fmaxf(1.f, cy);
            else                per = 0.5f * ((xacc[qq] + pbuf[qq]) / fmaxf(1.f, cy)
                                            + (xacc[5 + qq] + pbuf[5 + qq]) / fmaxf(1.f, cx));
            nzsum += per;
        }
        float2 res;
        res.x = nzsum;
        res.y = mNR[0] / fmaxf(1.f, (float)(offY[1] - offY[0]));
        g_batch[b] = res;
        __threadfence();                         // order STG before ticket
        fl = (atomicAdd(&g_ticket, 1) == BATCH - 1);
    }
    __syncthreads();                             // #5: broadcast fl
    if (!fl) return;

    // ---- Last CTA: final combine over 64 batches ----
    __threadfence();                             // acquire all g_batch
    if (tid < BATCH) {
        const float2 vv = __ldcg(&g_batch[tid]);
        snz[tid] = vv.x;
        szz[tid] = vv.y;
    }
    __syncthreads();
    if (tid < 32) {
        float a = snz[tid] + snz[tid + 32];
        float c = szz[tid] + szz[tid + 32];
#pragma unroll
        for (int o = 16; o; o >>= 1) {
            a += __shfl_down_sync(0xffffffffu, a, o);
            c += __shfl_down_sync(0xffffffffu, c, o);
        }
        if (tid == 0) {
            out[0] = a / (float)BATCH;
            if (out_size > 1) out[1] = c / (float)BATCH;
            g_ticket = 0;                        // reset for next graph replay
        }
    }
}

extern "C" void kernel_launch(void* const* d_in, const int* in_sizes, int n_in,
                              void* d_out, int out_size)
{
    const float4* target = (const float4*)d_in[0];
    const float4* reco   = (const float4*)d_in[1];
    const int*    ipid   = (const int*)d_in[2];
    const int*    opid   = (const int*)d_in[3];
    float*        out    = (float*)d_out;
    (void)in_sizes; (void)n_in;

    chamfer_fused<<<GRID, BLK>>>(target, reco, ipid, opid, out, out_size);
}

// round 11
// speedup vs baseline: 1.2879x; 1.2121x over previous
#include <cuda_runtime.h>
#include <math.h>

#define BATCH 64
#define NPART 512
#define BLK   1024               // 32 warps per CTA
#define GRID  (BATCH * 2)        // 128 CTAs = 64 clusters of 2
#define NW    (BLK / 32)
#define NGRP  16                 // binning groups per side

// Scratch (no allocation allowed).
__device__ float2 g_batch[BATCH];     // per-batch (nz, zz)
__device__ int    g_ticket;           // global arrival counter (reset in-kernel)

__device__ __forceinline__ unsigned smem_u32(const void* p) {
    unsigned a;
    asm("{ .reg .u64 t; cvta.to.shared.u64 t, %1; cvt.u32.u64 %0, t; }"
        : "=r"(a) : "l"(p));
    return a;
}
__device__ __forceinline__ unsigned mapa_rank(unsigned addr, unsigned rank) {
    unsigned r;
    asm("mapa.shared::cluster.u32 %0, %1, %2;" : "=r"(r) : "r"(addr), "r"(rank));
    return r;
}

__global__ __launch_bounds__(BLK) __cluster_dims__(2, 1, 1)
void chamfer_fused(const float4* __restrict__ target,
                   const float4* __restrict__ reco,
                   const int*    __restrict__ in_pid,
                   const int*    __restrict__ out_pid,
                   float* __restrict__ out, int out_size)
{
    __shared__ float4 sT[NPART], sR[NPART];      // class-compacted particles
    __shared__ float  sQT[NPART], sQR[NPART];    // 0.5*|p|^2 (compacted)
    __shared__ int    bX[NGRP][5], bY[NGRP][5];  // group counts -> group prefixes
    __shared__ int    offX[6], offY[6];
    __shared__ float  xacc[10];                  // [1..4]=sum_xy, [6..9]=sum_yx
    __shared__ float  pbuf[10];                  // partner partials (st.async dest)
    __shared__ alignas(8) unsigned long long mbar;  // rank0's arrival barrier
    __shared__ float  mNT[5], mNR[5];            // per-class norm sums (rank0 only)
    __shared__ float  snz[BATCH], szz[BATCH];    // final gather (last CTA)
    __shared__ int    fl;

    const int b    = blockIdx.x >> 1;
    const int s    = blockIdx.x & 1;             // cluster rank
    const int tid  = threadIdx.x;
    const int w    = tid >> 5;
    const int lane = tid & 31;
    const int side = tid >> 9;                   // 0 = target, 1 = reco (load phase)
    const int i    = tid & (NPART - 1);          // particle index within side
    const int g    = w & (NGRP - 1);             // binning group within side
    const unsigned lt = (1u << lane) - 1u;

    // rank0: init export barrier FIRST (remote st.asyncs arrive much later)
    if (s == 0 && tid == 0) {
        const unsigned mb = smem_u32(&mbar);
        asm volatile("mbarrier.init.shared.b64 [%0], 1;" :: "r"(mb) : "memory");
        asm volatile("fence.mbarrier_init.release.cluster;" ::: "memory");
    }
    if (tid < 10) xacc[tid] = 0.f;
    if (lane < 5) { if (side) bY[g][lane] = 0; else bX[g][lane] = 0; }
    __syncwarp();

    // ---- Load (1 particle per thread) + atomic-free binning ----
    const float4 v = side ? reco[b * NPART + i]    : target[b * NPART + i];
    const int    p = side ? out_pid[b * NPART + i] : in_pid[b * NPART + i];

    const unsigned mm = __match_any_sync(0xffffffffu, p);  // warp is side-uniform
    const int rk = __popc(mm & lt);
    if (rk == 0) { if (side) bY[g][p] = __popc(mm); else bX[g][p] = __popc(mm); }
    __syncthreads();                             // #1: all bins visible

    // ---- Scan (inside warp 0) ----
    if (w == 0) {
        int run = 0;
        if (tid < 10) {
            const int sd = tid / 5, q = tid % 5;
            int (*bb)[5] = sd ? bY : bX;
            int vv[NGRP];
#pragma unroll
            for (int gg = 0; gg < NGRP; gg++) vv[gg] = bb[gg][q];
#pragma unroll
            for (int gg = 0; gg < NGRP; gg++) { const int c = vv[gg]; bb[gg][q] = run; run += c; }
        }
        __syncwarp();
        {
            int a0 = 0, a1 = 0;
            const int myrun = (tid < 10) ? run : 0;
#pragma unroll
            for (int q = 0; q < 5; q++) {
                const int tX = __shfl_sync(0xffffffffu, myrun, q);
                const int tY = __shfl_sync(0xffffffffu, myrun, 5 + q);
                if (tid == 0) { offX[q] = a0; a0 += tX; }
                if (tid == 1) { offY[q] = a1; a1 += tY; }
            }
            if (tid == 0) offX[5] = a0;
            if (tid == 1) offY[5] = a1;
        }
    }
    __syncthreads();                             // #2: prefixed bins + offsets

    // ---- Deterministic scatter (no atomics): particle + half-sq-norm ----
    {
        const float q2 = v.x*v.x + v.y*v.y + v.z*v.z + v.w*v.w;
        if (side) {
            const int iy = offY[p] + bY[g][p] + rk;
            sR[iy] = v;  sQR[iy] = 0.5f * q2;
        } else {
            const int ix = offX[p] + bX[g][p] + rk;
            sT[ix] = v;  sQT[ix] = 0.5f * q2;
        }
    }
    __syncthreads();                             // #3: compacted arrays visible

    // ---- Per-class norm sums (rank 0 only; off the tail) ----
    if (s == 0 && w < 9) {
        const int seg = w;
        int lo, hi; const float* qq;
        if (seg < 4) { qq = sQT; lo = offX[seg + 1]; hi = offX[seg + 2]; }
        else         { qq = sQR; lo = offY[seg - 4]; hi = offY[seg - 3]; }
        float sum = 0.f;
        for (int j = lo + lane; j < hi; j += 32) sum += sqrtf(2.f * qq[j]);
#pragma unroll
        for (int o = 16; o; o >>= 1) sum += __shfl_down_sync(0xffffffffu, sum, o);
        if (lane == 0) {
            if (seg < 4)       mNT[seg + 1] = sum;
            else if (seg == 4) mNR[0]       = sum;
            else               mNR[seg - 4] = sum;
        }
    }

    // ---- Main work: warp-tiled, BROADCAST y-loads ----
    // Warp owns a 32-item x-tile of (pass, class); x in registers, one per lane.
    // min_j |x-y_j|^2 = |x|^2 + 2*min_j(h_j - x.y_j),  h_j = 0.5|y_j|^2
    // 64 warps/cluster = 2 passes x 4 classes x 8 tiles (covers class size <= 256).
    {
        const int gw   = s * NW + w;             // 0..63
        const int pass = gw >> 5;                // 0: targets-as-x, 1: recos-as-x
        const int cls  = ((gw >> 3) & 3) + 1;    // 1..4
        const int tile = gw & 7;

        const int*    offS = pass ? offY : offX;
        const int*    offO = pass ? offX : offY;
        const float4* xs   = pass ? sR  : sT;
        const float*  xq   = pass ? sQR : sQT;
        const float4* ys   = pass ? sT  : sR;
        const float*  yq   = pass ? sQT : sQR;

        const int lo = offS[cls] + tile * 32;
        const int hi = offS[cls + 1];
        const int jb = offO[cls], je = offO[cls + 1];

        if (lo < hi && jb < je) {
            const int  kx    = lo + lane;
            const bool valid = (kx < hi);
            const int  kc    = valid ? kx : lo;  // clamp: lo < hi <= NPART
            const float4 x   = xs[kc];
            const float  xsq = 2.f * xq[kc];
            const float nx = -x.x, ny = -x.y, nz = -x.z, nw = -x.w;

            float ms0 = INFINITY, ms1 = INFINITY;
            int j = jb;
            if ((je - jb) & 1) {
                const float4 y = ys[j];          // broadcast LDS
                ms0 = fmaf(nx, y.x, fmaf(ny, y.y, fmaf(nz, y.z, fmaf(nw, y.w, yq[j]))));
                j++;
            }
#pragma unroll 2
            for (; j < je; j += 2) {
                const float4 y0 = ys[j];
                const float4 y1 = ys[j + 1];
                const float s0 = fmaf(nx, y0.x, fmaf(ny, y0.y, fmaf(nz, y0.z, fmaf(nw, y0.w, yq[j]))));
                const float s1 = fmaf(nx, y1.x, fmaf(ny, y1.y, fmaf(nz, y1.z, fmaf(nw, y1.w, yq[j + 1]))));
                ms0 = fminf(ms0, s0);
                ms1 = fminf(ms1, s1);
            }
            const float ms = fminf(ms0, ms1);
            float d = valid ? sqrtf(fmaxf(fmaf(2.f, ms, xsq), 0.f)) : 0.f;
#pragma unroll
            for (int o = 16; o; o >>= 1) d += __shfl_down_sync(0xffffffffu, d, o);
            if (lane == 0) atomicAdd(&xacc[pass * 5 + cls], d);
        }
    }
    __syncthreads();                             // #4: xacc final in both CTAs

    // ---- rank1: push partials into rank0's pbuf via st.async, then exit ----
    if (s == 1) {
        if (tid < 10) {
            const unsigned raddr = mapa_rank(smem_u32(&pbuf[tid]), 0);
            const unsigned rmbar = mapa_rank(smem_u32(&mbar), 0);
            const float vv = xacc[tid];
            asm volatile(
                "st.async.shared::cluster.mbarrier::complete_tx::bytes.b32 [%0], %1, [%2];"
                :: "r"(raddr), "r"(__float_as_uint(vv)), "r"(rmbar) : "memory");
        }
        return;
    }

    // ---- rank0: wait for partner's 40 bytes, combine, ticket ----
    if (tid == 0) {
        const unsigned mb = smem_u32(&mbar);
        asm volatile("mbarrier.arrive.expect_tx.shared.b64 _, [%0], 40;" :: "r"(mb) : "memory");
        unsigned done;
        asm volatile(
            "{\n\t.reg .pred p;\n\t"
            "WAITLP:\n\t"
            "mbarrier.try_wait.parity.acquire.cta.shared::cta.b64 p, [%1], 0, 0x989680;\n\t"
            "selp.b32 %0, 1, 0, p;\n\t"
            "@!p bra WAITLP;\n\t}"
            : "=r"(done) : "r"(mb) : "memory");

        float nzsum = 0.f;
#pragma unroll
        for (int qq = 1; qq < 5; qq++) {
            const float cx = (float)(offX[qq + 1] - offX[qq]);
            const float cy = (float)(offY[qq + 1] - offY[qq]);
            float per;
            if (cy == 0.f)      per = mNT[qq] / fmaxf(1.f, cx);
            else if (cx == 0.f) per = mNR[qq] / fmaxf(1.f, cy);
            else                per = 0.5f * ((xacc[qq] + pbuf[qq]) / fmaxf(1.f, cy)
                                            + (xacc[5 + qq] + pbuf[5 + qq]) / fmaxf(1.f, cx));
            nzsum += per;
        }
        float2 res;
        res.x = nzsum;
        res.y = mNR[0] / fmaxf(1.f, (float)(offY[1] - offY[0]));
        g_batch[b] = res;
        __threadfence();                         // order STG before ticket
        fl = (atomicAdd(&g_ticket, 1) == BATCH - 1);
    }
    __syncthreads();                             // #5: broadcast fl
    if (!fl) return;

    // ---- Last CTA: final combine over 64 batches ----
    __threadfence();                             // acquire all g_batch
    if (tid < BATCH) {
        const float2 vv = __ldcg(&g_batch[tid]);
        snz[tid] = vv.x;
        szz[tid] = vv.y;
    }
    __syncthreads();
    if (tid < 32) {
        float a = snz[tid] + snz[tid + 32];
        float c = szz[tid] + szz[tid + 32];
#pragma unroll
        for (int o = 16; o; o >>= 1) {
            a += __shfl_down_sync(0xffffffffu, a, o);
            c += __shfl_down_sync(0xffffffffu, c, o);
        }
        if (tid == 0) {
            out[0] = a / (float)BATCH;
            if (out_size > 1) out[1] = c / (float)BATCH;
            g_ticket = 0;                        // reset for next graph replay
        }
    }
}

extern "C" void kernel_launch(void* const* d_in, const int* in_sizes, int n_in,
                              void* d_out, int out_size)
{
    const float4* target = (const float4*)d_in[0];
    const float4* reco   = (const float4*)d_in[1];
    const int*    ipid   = (const int*)d_in[2];
    const int*    opid   = (const int*)d_in[3];
    float*        out    = (float*)d_out;
    (void)in_sizes; (void)n_in;

    chamfer_fused<<<GRID, BLK>>>(target, reco, ipid, opid, out, out_size);
}